// round 6
// baseline (speedup 1.0000x reference)
#include <cuda_runtime.h>
#include <cuda_fp16.h>
#include <math.h>

#define N_NODES 200000
#define N_EDGES 12800000
#define ALPHA   0.1f
#define DT      0.01f
#define EPS_    1e-9f
#define DIFF_   10.0f
#define HARD    1.57079632679489662f

#define EPT        16                      // edges per thread (N_EDGES % 16 == 0)
#define N_THREADS  (N_EDGES / EPT)         // 800,000

// Scratch (device globals — no allocation allowed)
__device__ __half2 g_uv[N_NODES];   // pre-rotated (u,v) = e^{-i phi}(x+iy)
__device__ float2  g_sum[N_NODES];  // per-node gathered sum, atomic-accumulated

// PDL primitives
__device__ __forceinline__ void pdl_wait()    { asm volatile("griddepcontrol.wait;" ::: "memory"); }
__device__ __forceinline__ void pdl_trigger() { asm volatile("griddepcontrol.launch_dependents;" ::: "memory"); }

// ---------------------------------------------------------------------------
// K1: per-node prep. uv[i] = e^{-i phi_i}(x_i + i y_i) as half2; zero g_sum.
// Triggers dependent (edge) launch as soon as its writes are issued.
// ---------------------------------------------------------------------------
__global__ void __launch_bounds__(256) uv_kernel(
    const float* __restrict__ phase,
    const float* __restrict__ xy)
{
    int i = blockIdx.x * blockDim.x + threadIdx.x;
    if (i < N_NODES) {
        float s, c;
        __sincosf(phase[i], &s, &c);
        float2 p = ((const float2*)xy)[i];
        g_uv[i]  = __floats2half2_rn(fmaf(c, p.x, s * p.y), fmaf(c, p.y, -s * p.x));
        g_sum[i] = make_float2(0.0f, 0.0f);
    }
    pdl_trigger();
}

// ---------------------------------------------------------------------------
// K2: single fused edge pass. Per thread: 16 consecutive edges.
// Streaming int4 loads of src/dst are independent of g_uv -> issue them
// BEFORE griddepcontrol.wait so they overlap the uv kernel's tail.
// Then 16 independent uv gathers (deep MLP) + register run-length scan +
// atomicAdd per run.
// ---------------------------------------------------------------------------
__global__ void __launch_bounds__(256) edge_kernel(
    const int* __restrict__ src,
    const int* __restrict__ dst)
{
    int t = blockIdx.x * blockDim.x + threadIdx.x;
    if (t >= N_THREADS) { pdl_wait(); pdl_trigger(); return; }
    int base = t * EPT;

    // Independent streaming loads (overlap with uv kernel via PDL)
    int4 s0 = __ldcs((const int4*)(src + base) + 0);
    int4 s1 = __ldcs((const int4*)(src + base) + 1);
    int4 s2 = __ldcs((const int4*)(src + base) + 2);
    int4 s3 = __ldcs((const int4*)(src + base) + 3);
    int4 d0 = __ldcs((const int4*)(dst + base) + 0);
    int4 d1 = __ldcs((const int4*)(dst + base) + 1);
    int4 d2 = __ldcs((const int4*)(dst + base) + 2);
    int4 d3 = __ldcs((const int4*)(dst + base) + 3);

    // Wait for uv_kernel's g_uv / g_sum writes to be visible
    pdl_wait();

    int k[EPT] = { s0.x, s0.y, s0.z, s0.w,  s1.x, s1.y, s1.z, s1.w,
                   s2.x, s2.y, s2.z, s2.w,  s3.x, s3.y, s3.z, s3.w };
    int di[EPT] = { d0.x, d0.y, d0.z, d0.w,  d1.x, d1.y, d1.z, d1.w,
                    d2.x, d2.y, d2.z, d2.w,  d3.x, d3.y, d3.z, d3.w };

    // Launch all gathers (independent -> 16-deep MLP)
    __half2 h[EPT];
    #pragma unroll
    for (int e = 0; e < EPT; e++) h[e] = __ldg(&g_uv[di[e]]);

    // Run-length scan over sorted keys
    int   cur = k[0];
    float2 f0 = __half22float2(h[0]);
    float U = f0.x, V = f0.y;
    #pragma unroll
    for (int e = 1; e < EPT; e++) {
        float2 f = __half22float2(h[e]);
        if (k[e] != cur) {
            atomicAdd(&g_sum[cur].x, U);
            atomicAdd(&g_sum[cur].y, V);
            cur = k[e];
            U = f.x; V = f.y;
        } else {
            U += f.x; V += f.y;
        }
    }
    atomicAdd(&g_sum[cur].x, U);
    atomicAdd(&g_sum[cur].y, V);

    pdl_trigger();
}

// ---------------------------------------------------------------------------
// K3: thread-per-node finalize. Issues all g_sum-independent loads BEFORE
// the PDL wait so they overlap the edge kernel's tail.
// ---------------------------------------------------------------------------
__global__ void __launch_bounds__(256) finalize_kernel(
    const float* __restrict__ phase,
    const float* __restrict__ xy,
    const float* __restrict__ xy_dot_old,
    const float* __restrict__ w,
    const float* __restrict__ amp,
    const float* __restrict__ ha,
    float*       __restrict__ out)
{
    int i = blockIdx.x * blockDim.x + threadIdx.x;
    if (i >= N_NODES) { pdl_wait(); return; }

    // Independent input loads (overlap with edge kernel via PDL)
    float  ph = phase[i];
    float2 p  = ((const float2*)xy)[i];
    float2 pd = ((const float2*)xy_dot_old)[i];
    float  wi = w[i];
    float  am = amp[i];
    float  hi = ha[i];

    // Wait for edge kernel's atomics to be visible
    pdl_wait();
    float2 sv = g_sum[i];

    float s, c;
    __sincosf(ph, &s, &c);
    float sum_x = fmaf(c, sv.x, -s * sv.y);
    float sum_y = fmaf(s, sv.x,  c * sv.y);

    float r2   = fmaf(p.x, p.x, p.y * p.y);
    float a    = ALPHA * (1.0f - r2 * r2);
    float zeta = 1.0f - hi * ((pd.x + EPS_) / (fabsf(pd.x) + EPS_));
    float b    = wi / (zeta + EPS_);

    float kx = fmaf(a, p.x, -b * p.y);
    float ky = fmaf(b, p.x,  a * p.y);

    float x_dot = fminf(fmaxf(kx + sum_x, pd.x - DIFF_), pd.x + DIFF_);
    float y_dot = fminf(fmaxf(ky + sum_y, pd.y - DIFF_), pd.y + DIFF_);

    float xn = fmaf(x_dot, DT, p.x);
    float yn = fmaf(y_dot, DT, p.y);
    float ang = fminf(fmaxf(am * yn, -HARD), HARD);

    out[i] = ang;                                              // angles
    ((float2*)(out + N_NODES))[i]     = make_float2(xn, yn);   // xy_new
    ((float2*)(out + 3 * N_NODES))[i] = p;                     // xy_dot_old_new = xy
}

extern "C" void kernel_launch(void* const* d_in, const int* in_sizes, int n_in,
                              void* d_out, int out_size)
{
    const float* xy         = (const float*)d_in[0];
    const float* xy_dot_old = (const float*)d_in[1];
    const float* phase      = (const float*)d_in[2];
    const float* w          = (const float*)d_in[3];
    const float* amplitudes = (const float*)d_in[4];
    const float* ha         = (const float*)d_in[5];
    const int*   edge_src   = (const int*)d_in[6];
    const int*   edge_dst   = (const int*)d_in[7];
    float* out = (float*)d_out;

    int nb_nodes = (N_NODES + 255) / 256;
    int nb_edge  = (N_THREADS + 255) / 256;

    cudaLaunchAttribute pdl_attr[1];
    pdl_attr[0].id = cudaLaunchAttributeProgrammaticStreamSerialization;
    pdl_attr[0].val.programmaticStreamSerializationAllowed = 1;

    // K1: plain launch
    uv_kernel<<<nb_nodes, 256>>>(phase, xy);

    // K2: PDL — may start while K1 drains; waits internally before gathers
    {
        cudaLaunchConfig_t cfg = {};
        cfg.gridDim  = dim3(nb_edge);
        cfg.blockDim = dim3(256);
        cfg.stream   = 0;
        cfg.attrs    = pdl_attr;
        cfg.numAttrs = 1;
        cudaLaunchKernelEx(&cfg, edge_kernel, edge_src, edge_dst);
    }

    // K3: PDL — may start while K2 drains; waits internally before g_sum read
    {
        cudaLaunchConfig_t cfg = {};
        cfg.gridDim  = dim3(nb_nodes);
        cfg.blockDim = dim3(256);
        cfg.stream   = 0;
        cfg.attrs    = pdl_attr;
        cfg.numAttrs = 1;
        cudaLaunchKernelEx(&cfg, finalize_kernel, phase, xy, xy_dot_old, w,
                           amplitudes, ha, out);
    }
}

// round 7
// speedup vs baseline: 1.0347x; 1.0347x over previous
#include <cuda_runtime.h>
#include <cuda_fp16.h>
#include <math.h>

#define N_NODES 200000
#define N_EDGES 12800000
#define ALPHA   0.1f
#define DT      0.01f
#define EPS_    1e-9f
#define DIFF_   10.0f
#define HARD    1.57079632679489662f

#define EPT        16                      // edges per thread (N_EDGES % 16 == 0)
#define N_THREADS  (N_EDGES / EPT)         // 800,000 (multiple of 32)

// Scratch (device globals — no allocation allowed)
__device__ __half2 g_uv[N_NODES];   // pre-rotated (u,v) = e^{-i phi}(x+iy)
__device__ float2  g_sum[N_NODES];  // per-node gathered sum, atomic-accumulated

__device__ __forceinline__ void pdl_wait()    { asm volatile("griddepcontrol.wait;" ::: "memory"); }
__device__ __forceinline__ void pdl_trigger() { asm volatile("griddepcontrol.launch_dependents;" ::: "memory"); }

// ---------------------------------------------------------------------------
// K1: per-node prep, 2 nodes/thread for ILP. uv = e^{-i phi}(x+iy) as half2.
// ---------------------------------------------------------------------------
__global__ void __launch_bounds__(256) uv_kernel(
    const float* __restrict__ phase,
    const float* __restrict__ xy)
{
    int t = blockIdx.x * blockDim.x + threadIdx.x;
    int i = 2 * t;
    if (i < N_NODES) {
        float2 ph = ((const float2*)phase)[t];
        float4 p  = ((const float4*)xy)[t];          // (x0,y0,x1,y1)
        float s0, c0, s1, c1;
        __sincosf(ph.x, &s0, &c0);
        __sincosf(ph.y, &s1, &c1);
        __half2 u0 = __floats2half2_rn(fmaf(c0, p.x, s0 * p.y), fmaf(c0, p.y, -s0 * p.x));
        __half2 u1 = __floats2half2_rn(fmaf(c1, p.z, s1 * p.w), fmaf(c1, p.w, -s1 * p.z));
        *((uint2*)&g_uv[i]) = make_uint2(*(unsigned*)&u0, *(unsigned*)&u1);
        ((float4*)g_sum)[t] = make_float4(0.f, 0.f, 0.f, 0.f);
    }
    pdl_trigger();
}

// ---------------------------------------------------------------------------
// K2: fused edge pass. 16 edges/thread: coalesced int4 streams, 16-deep
// gather MLP, register run-length scan. Interior runs flush via atomics;
// each thread's final pending run goes through a warp shfl segmented merge
// so only the last lane of each key-run flushes (atomics cut ~2.4x).
// ---------------------------------------------------------------------------
__global__ void __launch_bounds__(256) edge_kernel(
    const int* __restrict__ src,
    const int* __restrict__ dst)
{
    int t = blockIdx.x * blockDim.x + threadIdx.x;
    int lane = threadIdx.x & 31;
    bool active = (t < N_THREADS);
    int base = active ? t * EPT : (N_THREADS - 1) * EPT;

    // Independent streaming loads (before PDL wait)
    int4 s0 = __ldcs((const int4*)(src + base) + 0);
    int4 s1 = __ldcs((const int4*)(src + base) + 1);
    int4 s2 = __ldcs((const int4*)(src + base) + 2);
    int4 s3 = __ldcs((const int4*)(src + base) + 3);
    int4 d0 = __ldcs((const int4*)(dst + base) + 0);
    int4 d1 = __ldcs((const int4*)(dst + base) + 1);
    int4 d2 = __ldcs((const int4*)(dst + base) + 2);
    int4 d3 = __ldcs((const int4*)(dst + base) + 3);

    pdl_wait();

    int k[EPT] = { s0.x, s0.y, s0.z, s0.w,  s1.x, s1.y, s1.z, s1.w,
                   s2.x, s2.y, s2.z, s2.w,  s3.x, s3.y, s3.z, s3.w };
    int di[EPT] = { d0.x, d0.y, d0.z, d0.w,  d1.x, d1.y, d1.z, d1.w,
                    d2.x, d2.y, d2.z, d2.w,  d3.x, d3.y, d3.z, d3.w };

    __half2 h[EPT];
    #pragma unroll
    for (int e = 0; e < EPT; e++) h[e] = __ldg(&g_uv[di[e]]);

    // Run-length scan; interior flushes only
    int   cur = k[0];
    float2 f0 = __half22float2(h[0]);
    float U = f0.x, V = f0.y;
    #pragma unroll
    for (int e = 1; e < EPT; e++) {
        float2 f = __half22float2(h[e]);
        if (k[e] != cur) {
            if (active) {
                atomicAdd(&g_sum[cur].x, U);
                atomicAdd(&g_sum[cur].y, V);
            }
            cur = k[e];
            U = f.x; V = f.y;
        } else {
            U += f.x; V += f.y;
        }
    }

    // Warp segmented merge of pending runs (keys nondecreasing across lanes).
    if (!active) { U = 0.0f; V = 0.0f; cur = -1; }
    #pragma unroll
    for (int o = 1; o < 32; o <<= 1) {
        int   pk = __shfl_up_sync(0xffffffffu, cur, o);
        float pU = __shfl_up_sync(0xffffffffu, U, o);
        float pV = __shfl_up_sync(0xffffffffu, V, o);
        if (lane >= o && pk == cur) { U += pU; V += pV; }
    }
    int nk = __shfl_down_sync(0xffffffffu, cur, 1);
    if (active && (lane == 31 || nk != cur)) {
        atomicAdd(&g_sum[cur].x, U);
        atomicAdd(&g_sum[cur].y, V);
    }

    pdl_trigger();
}

// ---------------------------------------------------------------------------
// K3: thread-per-node finalize. g_sum-independent loads before PDL wait.
// ---------------------------------------------------------------------------
__global__ void __launch_bounds__(256) finalize_kernel(
    const float* __restrict__ phase,
    const float* __restrict__ xy,
    const float* __restrict__ xy_dot_old,
    const float* __restrict__ w,
    const float* __restrict__ amp,
    const float* __restrict__ ha,
    float*       __restrict__ out)
{
    int i = blockIdx.x * blockDim.x + threadIdx.x;
    if (i >= N_NODES) { pdl_wait(); return; }

    float  ph = phase[i];
    float2 p  = ((const float2*)xy)[i];
    float2 pd = ((const float2*)xy_dot_old)[i];
    float  wi = w[i];
    float  am = amp[i];
    float  hi = ha[i];

    pdl_wait();
    float2 sv = g_sum[i];

    float s, c;
    __sincosf(ph, &s, &c);
    float sum_x = fmaf(c, sv.x, -s * sv.y);
    float sum_y = fmaf(s, sv.x,  c * sv.y);

    float r2   = fmaf(p.x, p.x, p.y * p.y);
    float a    = ALPHA * (1.0f - r2 * r2);
    float zeta = 1.0f - hi * ((pd.x + EPS_) / (fabsf(pd.x) + EPS_));
    float b    = wi / (zeta + EPS_);

    float kx = fmaf(a, p.x, -b * p.y);
    float ky = fmaf(b, p.x,  a * p.y);

    float x_dot = fminf(fmaxf(kx + sum_x, pd.x - DIFF_), pd.x + DIFF_);
    float y_dot = fminf(fmaxf(ky + sum_y, pd.y - DIFF_), pd.y + DIFF_);

    float xn = fmaf(x_dot, DT, p.x);
    float yn = fmaf(y_dot, DT, p.y);
    float ang = fminf(fmaxf(am * yn, -HARD), HARD);

    out[i] = ang;                                              // angles
    ((float2*)(out + N_NODES))[i]     = make_float2(xn, yn);   // xy_new
    ((float2*)(out + 3 * N_NODES))[i] = p;                     // xy_dot_old_new = xy
}

extern "C" void kernel_launch(void* const* d_in, const int* in_sizes, int n_in,
                              void* d_out, int out_size)
{
    const float* xy         = (const float*)d_in[0];
    const float* xy_dot_old = (const float*)d_in[1];
    const float* phase      = (const float*)d_in[2];
    const float* w          = (const float*)d_in[3];
    const float* amplitudes = (const float*)d_in[4];
    const float* ha         = (const float*)d_in[5];
    const int*   edge_src   = (const int*)d_in[6];
    const int*   edge_dst   = (const int*)d_in[7];
    float* out = (float*)d_out;

    int nb_uv    = ((N_NODES + 1) / 2 + 255) / 256;
    int nb_edge  = (N_THREADS + 255) / 256;
    int nb_nodes = (N_NODES + 255) / 256;

    cudaLaunchAttribute pdl_attr[1];
    pdl_attr[0].id = cudaLaunchAttributeProgrammaticStreamSerialization;
    pdl_attr[0].val.programmaticStreamSerializationAllowed = 1;

    uv_kernel<<<nb_uv, 256>>>(phase, xy);

    {
        cudaLaunchConfig_t cfg = {};
        cfg.gridDim  = dim3(nb_edge);
        cfg.blockDim = dim3(256);
        cfg.stream   = 0;
        cfg.attrs    = pdl_attr;
        cfg.numAttrs = 1;
        cudaLaunchKernelEx(&cfg, edge_kernel, edge_src, edge_dst);
    }
    {
        cudaLaunchConfig_t cfg = {};
        cfg.gridDim  = dim3(nb_nodes);
        cfg.blockDim = dim3(256);
        cfg.stream   = 0;
        cfg.attrs    = pdl_attr;
        cfg.numAttrs = 1;
        cudaLaunchKernelEx(&cfg, finalize_kernel, phase, xy, xy_dot_old, w,
                           amplitudes, ha, out);
    }
}